// round 14
// baseline (speedup 1.0000x reference)
#include <cuda_runtime.h>
#include <math.h>

#define BS 256
#define T_ 128
#define HID 256
#define G3 768
#define NBG 144
#define Y_OFF 8388608
#define R_OFF 8388864
#define A_OFF 16777472
#define L_OFF 16777728

#define SMEM_GRU 167936
#define SMEM_GEMM (2*2*32*130*4)

typedef unsigned long long ull;
union F2 { ull u; float2 f; };
#define FMA2(a,x,y) asm("fma.rn.f32x2 %0,%1,%2,%0;" : "+l"(a) : "l"(x), "l"(y))
__device__ __forceinline__ ull pack2(float v){ ull r; asm("mov.b64 %0,{%1,%1};" : "=l"(r) : "f"(v)); return r; }

__device__ float g_GI0[BS*T_*G3];     // layout: [t][b][768]
__device__ float g_gi1[2][BS*G3];
__device__ float g_h1[2][BS*HID];
__device__ float g_h2[2][BS*HID];
__device__ float g_WC[BS*T_*HID];
__device__ float g_G[BS*T_*HID];
__device__ float g_Wcat[512*HID];
__device__ float g_part[(T_-1)*BS];
__device__ float g_dummy;
__device__ unsigned g_cnt;
__device__ unsigned g_gen;
// sliced epochs: grp0-2 -> idx grp*4+rt (width 8); grp3 -> idx 12+rt3 (width 4)
__device__ volatile int g_eps[20];
__device__ unsigned g_acnt[20];

__device__ __forceinline__ float sigm(float x){ return 1.f/(1.f+expf(-x)); }
__device__ __forceinline__ float gelu_f(float x){ return 0.5f*x*(1.f+erff(x*0.70710678118654752f)); }

__device__ __forceinline__ void gbar(unsigned nb){
  __syncthreads();
  if (threadIdx.x==0){
    __threadfence();
    unsigned g = *(volatile unsigned*)&g_gen;
    if (atomicAdd(&g_cnt,1u)==nb-1u){
      g_cnt = 0u;
      __threadfence();
      atomicAdd(&g_gen,1u);
    } else {
      while (*(volatile unsigned*)&g_gen == g) __nanosleep(32);
      __threadfence();
    }
  }
  __syncthreads();
}

__device__ __forceinline__ void wait_ep(int sl, int need){
  while (g_eps[sl] < need) __nanosleep(32);
}

__global__ void pad_k(){ if (threadIdx.x==0) g_dummy = 0.f; }

// ======== gemm_tc: C = act(A[Mx256](lda) @ B[Nx256]^T + bias); optional row permute ========
__global__ void __launch_bounds__(512) gemm_tc(
    const float* __restrict__ A, int lda,
    const float* __restrict__ B,
    const float* __restrict__ bias,
    float* __restrict__ C, int ldc, int act,
    float* __restrict__ C2, int perm)
{
  extern __shared__ float gsm[];
  float* SA = gsm;
  float* SB = gsm + 2*32*130;
  const int bm = blockIdx.y*128, bn = blockIdx.x*128;
  const int tid = threadIdx.x;
  const int wg = tid>>5, tx = tid&31;
  const int lrow = tid>>3, lkq = tid&7;

  ull acc[4][4];
  #pragma unroll
  for (int c=0;c<4;c++){ acc[c][0]=0; acc[c][1]=0; acc[c][2]=0; acc[c][3]=0; }

  float4 pa0 = *(const float4*)(A + (size_t)(bm+lrow)*lda + lkq*4);
  float4 pa1 = *(const float4*)(A + (size_t)(bm+lrow+64)*lda + lkq*4);
  float4 pb0 = *(const float4*)(B + (size_t)(bn+lrow)*256 + lkq*4);
  float4 pb1 = *(const float4*)(B + (size_t)(bn+lrow+64)*256 + lkq*4);
  {
    float* dA = SA; float* dB = SB;
    dA[(lkq*4+0)*130+lrow]=pa0.x; dA[(lkq*4+1)*130+lrow]=pa0.y; dA[(lkq*4+2)*130+lrow]=pa0.z; dA[(lkq*4+3)*130+lrow]=pa0.w;
    dA[(lkq*4+0)*130+lrow+64]=pa1.x; dA[(lkq*4+1)*130+lrow+64]=pa1.y; dA[(lkq*4+2)*130+lrow+64]=pa1.z; dA[(lkq*4+3)*130+lrow+64]=pa1.w;
    dB[(lkq*4+0)*130+lrow]=pb0.x; dB[(lkq*4+1)*130+lrow]=pb0.y; dB[(lkq*4+2)*130+lrow]=pb0.z; dB[(lkq*4+3)*130+lrow]=pb0.w;
    dB[(lkq*4+0)*130+lrow+64]=pb1.x; dB[(lkq*4+1)*130+lrow+64]=pb1.y; dB[(lkq*4+2)*130+lrow+64]=pb1.z; dB[(lkq*4+3)*130+lrow+64]=pb1.w;
  }
  __syncthreads();

  #pragma unroll 1
  for (int kc=0; kc<8; kc++){
    const float* cA = SA + (kc&1)*4160;
    const float* cB = SB + (kc&1)*4160;
    if (kc<7){
      pa0 = *(const float4*)(A + (size_t)(bm+lrow)*lda + (kc+1)*32 + lkq*4);
      pa1 = *(const float4*)(A + (size_t)(bm+lrow+64)*lda + (kc+1)*32 + lkq*4);
      pb0 = *(const float4*)(B + (size_t)(bn+lrow)*256 + (kc+1)*32 + lkq*4);
      pb1 = *(const float4*)(B + (size_t)(bn+lrow+64)*256 + (kc+1)*32 + lkq*4);
    }
    #pragma unroll
    for (int k=0;k<32;k++){
      ull a0=*(const ull*)&cA[k*130 + wg*8];
      ull a1=*(const ull*)&cA[k*130 + wg*8+2];
      ull a2=*(const ull*)&cA[k*130 + wg*8+4];
      ull a3=*(const ull*)&cA[k*130 + wg*8+6];
      #pragma unroll
      for (int c=0;c<4;c++){
        ull bb = pack2(cB[k*130 + tx+32*c]);
        FMA2(acc[c][0],a0,bb); FMA2(acc[c][1],a1,bb);
        FMA2(acc[c][2],a2,bb); FMA2(acc[c][3],a3,bb);
      }
    }
    if (kc<7){
      float* dA = SA + ((kc+1)&1)*4160;
      float* dB = SB + ((kc+1)&1)*4160;
      dA[(lkq*4+0)*130+lrow]=pa0.x; dA[(lkq*4+1)*130+lrow]=pa0.y; dA[(lkq*4+2)*130+lrow]=pa0.z; dA[(lkq*4+3)*130+lrow]=pa0.w;
      dA[(lkq*4+0)*130+lrow+64]=pa1.x; dA[(lkq*4+1)*130+lrow+64]=pa1.y; dA[(lkq*4+2)*130+lrow+64]=pa1.z; dA[(lkq*4+3)*130+lrow+64]=pa1.w;
      dB[(lkq*4+0)*130+lrow]=pb0.x; dB[(lkq*4+1)*130+lrow]=pb0.y; dB[(lkq*4+2)*130+lrow]=pb0.z; dB[(lkq*4+3)*130+lrow]=pb0.w;
      dB[(lkq*4+0)*130+lrow+64]=pb1.x; dB[(lkq*4+1)*130+lrow+64]=pb1.y; dB[(lkq*4+2)*130+lrow+64]=pb1.z; dB[(lkq*4+3)*130+lrow+64]=pb1.w;
    }
    __syncthreads();
  }

  #pragma unroll
  for (int c=0;c<4;c++){
    int col = bn + tx + 32*c;
    float bv = bias ? bias[col] : 0.f;
    #pragma unroll
    for (int p=0;p<4;p++){
      F2 u; u.u = acc[c][p];
      float v[2] = {u.f.x, u.f.y};
      #pragma unroll
      for (int h=0;h<2;h++){
        float o = v[h] + bv;
        size_t r = (size_t)(bm + wg*8 + 2*p + h);
        if (perm) r = (size_t)(r & 127)*256 + (r >> 7);
        if (C2 && col >= 256){
          C2[r*ldc + (col-256)] = gelu_f(o);
        } else {
          if (act) o = gelu_f(o);
          C[r*ldc + col] = o;
        }
      }
    }
  }
}

// ======== persistent fused GRU + heads: 144 CTAs x 512 threads, rt-sliced epoch sync ========
__global__ void __launch_bounds__(512,1) gru_kernel(
    const float* __restrict__ Whh0, const float* __restrict__ bhh0,
    const float* __restrict__ Wih1, const float* __restrict__ bih1,
    const float* __restrict__ Whh1, const float* __restrict__ bhh1,
    const float* __restrict__ Wr2,
    float* __restrict__ H)
{
  extern __shared__ float sm[];
  const int cta = blockIdx.x, tid = threadIdx.x;
  const int grp = cta>>5;

  float* wsm = sm;
  float* sAT = sm + 96*256;
  const int loc = cta&31;
  const int rt = loc>>3, ct = loc&7;
  const int lo = tid & 255, half = tid >> 8;
  const int rg = lo>>4, tx = lo&15;
  const int rg4 = rg*4;
  const int row0 = rt*64 + rg4;
  const int col2 = ct*32 + tx*2;
  const bool is0 = (grp==0), is1 = (grp==1), is2 = (grp==2);

  const float* WB = is0 ? Whh0 : (is1 ? Wih1 : Whh1);
  const float* bvp = is0 ? bhh0 : (is1 ? bih1 : bhh1);
  float2 bR = *(const float2*)(bvp+col2);
  float2 bZ = *(const float2*)(bvp+256+col2);
  float2 bN = *(const float2*)(bvp+512+col2);

  const int arow = tid>>3, akq = (tid&7)*4;

  float* wsm3 = sm;
  float* sA3  = sm + 32768;
  const int loc3 = cta - 96;
  const int rt3 = loc3>>2, ct3 = loc3&3;
  float* wsm4 = sm;
  float* sA4  = sm + 16384;
  const int loc4 = cta - 128;
  const int rt4 = loc4>>2, ct4 = loc4&3;
  const int w5 = tid>>5, lane = tid&31;
  const int lh = lane>>4, lx = lane&15;

  if (grp < 3){
    for (int i = tid; i < 96*64; i += 512){
      int c = i>>6, kk = i&63;
      int g = c>>5, cc = c&31;
      float4 w = *(const float4*)(WB + (size_t)(g*256 + ct*32 + cc)*256 + kk*4);
      wsm[(kk*4+0)*96 + c] = w.x;
      wsm[(kk*4+1)*96 + c] = w.y;
      wsm[(kk*4+2)*96 + c] = w.z;
      wsm[(kk*4+3)*96 + c] = w.w;
    }
  } else if (grp == 3){
    for (int i = tid; i < 128*64; i += 512){
      int c = i>>6, kq = (i&63)*4;
      float4 w = *(const float4*)(g_Wcat + (size_t)(ct3*128 + c)*256 + kq);
      wsm3[(kq+0)*128 + c] = w.x;
      wsm3[(kq+1)*128 + c] = w.y;
      wsm3[(kq+2)*128 + c] = w.z;
      wsm3[(kq+3)*128 + c] = w.w;
    }
  } else {
    for (int i = tid; i < 64*64; i += 512){
      int c = i>>6, kq = (i&63)*4;
      float4 w = *(const float4*)(Wr2 + (size_t)(ct4*64 + c)*256 + kq);
      wsm4[(kq+0)*64 + c] = w.x;
      wsm4[(kq+1)*64 + c] = w.y;
      wsm4[(kq+2)*64 + c] = w.z;
      wsm4[(kq+3)*64 + c] = w.w;
    }
  }
  for (int i = cta*512 + tid; i < BS*HID; i += NBG*512){
    g_h1[0][i] = 0.f; g_h2[1][i] = 0.f;
  }
  if (cta==0 && tid==0){
    #pragma unroll
    for (int s=0;s<20;s++){ g_acnt[s]=0u; g_eps[s]=0; }
  }
  gbar(NBG);

  #pragma unroll 1
  for (int p=0; p<T_+5; ++p){
    // ---- sliced epoch wait on true producers ----
    if (tid==0){
      if (grp==0){ wait_ep(0*4+rt,p); wait_ep(1*4+rt,p); }
      else if (grp==1){ wait_ep(0*4+rt,p); wait_ep(2*4+rt,p); }
      else if (grp==2){ wait_ep(1*4+rt,p); wait_ep(2*4+rt,p); }
      else if (grp==3){ wait_ep(2*4+(rt3>>1),p); }
      else { wait_ep(12+2*rt4,p-1); wait_ep(12+2*rt4+1,p-1); }
      __threadfence();
    }
    __syncthreads();

    if (grp < 3){
      bool active = (is0 && p<T_) || (is1 && p>=1 && p<=T_) || (is2 && p>=2 && p<=T_+1);
      if (active){
        const float* Ain = is2 ? g_h2[(p-1)&1] : g_h1[p&1];

        float2 gR[4], gZ[4], gN[4], hold[4];
        if (half==0){
          if (is0){
            #pragma unroll
            for (int j=0;j<4;j++){
              const float* gi = g_GI0 + ((size_t)p*256 + row0+j)*G3;
              gR[j]=*(const float2*)(gi+col2); gZ[j]=*(const float2*)(gi+256+col2); gN[j]=*(const float2*)(gi+512+col2);
            }
          } else if (is2){
            const float* gb = g_gi1[(p-1)&1];
            #pragma unroll
            for (int j=0;j<4;j++){
              const float* gi = gb + (size_t)(row0+j)*G3;
              gR[j]=*(const float2*)(gi+col2); gZ[j]=*(const float2*)(gi+256+col2); gN[j]=*(const float2*)(gi+512+col2);
            }
          }
        }

        {
          const float* arp = Ain + (size_t)(rt*64+arow)*256 + akq;
          #pragma unroll
          for (int c=0;c<8;c++){
            float4 v = *(const float4*)(arp + c*32);
            int kb = c*32 + akq;
            sAT[(kb+0)*66 + arow] = v.x;
            sAT[(kb+1)*66 + arow] = v.y;
            sAT[(kb+2)*66 + arow] = v.z;
            sAT[(kb+3)*66 + arow] = v.w;
          }
        }
        __syncthreads();

        if (half==0 && !is1){
          #pragma unroll
          for (int j=0;j<4;j++){
            hold[j].x = sAT[col2*66 + rg4+j];
            hold[j].y = sAT[(col2+1)*66 + rg4+j];
          }
        }

        ull acc[3][4];
        #pragma unroll
        for (int g=0;g<3;g++){ acc[g][0]=0; acc[g][1]=0; acc[g][2]=0; acc[g][3]=0; }

        const int kbase = half*128;
        #pragma unroll 1
        for (int kc=0; kc<4; kc++){
          #pragma unroll
          for (int kk=0;kk<32;kk++){
            int k = kbase + kc*32 + kk;
            float2 aA = *(const float2*)&sAT[k*66 + rg4];
            float2 aB = *(const float2*)&sAT[k*66 + rg4 + 2];
            ull a0 = pack2(aA.x), a1 = pack2(aA.y), a2 = pack2(aB.x), a3 = pack2(aB.y);
            const float* bk = wsm + k*96 + tx*2;
            ull b0 = *(const ull*)(bk);
            ull b1 = *(const ull*)(bk+32);
            ull b2 = *(const ull*)(bk+64);
            FMA2(acc[0][0],a0,b0); FMA2(acc[0][1],a1,b0); FMA2(acc[0][2],a2,b0); FMA2(acc[0][3],a3,b0);
            FMA2(acc[1][0],a0,b1); FMA2(acc[1][1],a1,b1); FMA2(acc[1][2],a2,b1); FMA2(acc[1][3],a3,b1);
            FMA2(acc[2][0],a0,b2); FMA2(acc[2][1],a1,b2); FMA2(acc[2][2],a2,b2); FMA2(acc[2][3],a3,b2);
          }
        }
        __syncthreads();

        ull* red = (ull*)sAT;
        if (half==1){
          #pragma unroll
          for (int g=0;g<3;g++)
            #pragma unroll
            for (int r=0;r<4;r++)
              red[((g*4+r)*256) + lo] = acc[g][r];
        }
        __syncthreads();

        if (half==0){
          #pragma unroll
          for (int g=0;g<3;g++)
            #pragma unroll
            for (int r=0;r<4;r++){
              F2 u,v; u.u=acc[g][r]; v.u=red[((g*4+r)*256) + lo];
              u.f.x += v.f.x; u.f.y += v.f.y;
              acc[g][r]=u.u;
            }
          #pragma unroll
          for (int j=0;j<4;j++){
            F2 u0,u1,u2;
            u0.u=acc[0][j]; u1.u=acc[1][j]; u2.u=acc[2][j];
            int b = row0 + j;
            if (is0){
              float r0 = sigm(gR[j].x + u0.f.x + bR.x), r1 = sigm(gR[j].y + u0.f.y + bR.y);
              float z0 = sigm(gZ[j].x + u1.f.x + bZ.x), z1 = sigm(gZ[j].y + u1.f.y + bZ.y);
              float n0 = tanhf(gN[j].x + r0*(u2.f.x + bN.x)), n1 = tanhf(gN[j].y + r1*(u2.f.y + bN.y));
              float2 o; o.x = (1.f-z0)*n0 + z0*hold[j].x; o.y = (1.f-z1)*n1 + z1*hold[j].y;
              *(float2*)(g_h1[(p+1)&1] + b*HID + col2) = o;
            } else if (is1){
              float* og = g_gi1[p&1] + (size_t)b*G3;
              float2 o;
              o.x = u0.f.x + bR.x; o.y = u0.f.y + bR.y; *(float2*)(og+col2) = o;
              o.x = u1.f.x + bZ.x; o.y = u1.f.y + bZ.y; *(float2*)(og+256+col2) = o;
              o.x = u2.f.x + bN.x; o.y = u2.f.y + bN.y; *(float2*)(og+512+col2) = o;
            } else {
              float r0 = sigm(gR[j].x + u0.f.x + bR.x), r1 = sigm(gR[j].y + u0.f.y + bR.y);
              float z0 = sigm(gZ[j].x + u1.f.x + bZ.x), z1 = sigm(gZ[j].y + u1.f.y + bZ.y);
              float n0 = tanhf(gN[j].x + r0*(u2.f.x + bN.x)), n1 = tanhf(gN[j].y + r1*(u2.f.y + bN.y));
              float2 o; o.x = (1.f-z0)*n0 + z0*hold[j].x; o.y = (1.f-z1)*n1 + z1*hold[j].y;
              *(float2*)(g_h2[p&1] + b*HID + col2) = o;
              *(float2*)(H + ((size_t)b*T_ + (p-2))*HID + col2) = o;
            }
          }
        }
      }
    } else if (grp == 3){
      if (p>=3 && p<=T_+2){
        const int t3 = p-3;
        #pragma unroll
        for (int q=0;q<4;q++){
          int idx = tid + 512*q;
          int row = idx & 31, kq = (idx>>5)*4;
          float4 v = *(const float4*)(H + ((size_t)(rt3*32+row)*T_ + t3)*256 + kq);
          sA3[(kq+0)*36 + row] = v.x;
          sA3[(kq+1)*36 + row] = v.y;
          sA3[(kq+2)*36 + row] = v.z;
          sA3[(kq+3)*36 + row] = v.w;
        }
        __syncthreads();
        const int r0 = (w5>>2)*8 + lh*4;
        const int cp = (w5&3)*16 + lx;
        ull acc3[4] = {0,0,0,0};
        #pragma unroll 1
        for (int kc=0;kc<8;kc++){
          #pragma unroll
          for (int kk=0;kk<32;kk++){
            int k = kc*32+kk;
            float4 av = *(const float4*)&sA3[k*36 + r0];
            ull b = *(const ull*)&wsm3[k*128 + cp*2];
            FMA2(acc3[0], pack2(av.x), b);
            FMA2(acc3[1], pack2(av.y), b);
            FMA2(acc3[2], pack2(av.z), b);
            FMA2(acc3[3], pack2(av.w), b);
          }
        }
        __syncthreads();
        const int gcol = ct3*128 + cp*2;
        #pragma unroll
        for (int j=0;j<4;j++){
          int b = rt3*32 + r0 + j;
          F2 u; u.u = acc3[j];
          if (gcol < 256){
            *(float2*)(g_WC + ((size_t)b*T_ + t3)*256 + gcol) = u.f;
          } else {
            float2 o; o.x = gelu_f(u.f.x); o.y = gelu_f(u.f.y);
            *(float2*)(g_G + ((size_t)b*T_ + t3)*256 + (gcol-256)) = o;
          }
        }
      }
    } else {
      if (p>=5 && p<=T_+4){
        const int t4 = p-5;
        #pragma unroll
        for (int q=0;q<8;q++){
          int idx = tid + 512*q;
          int row = idx & 63, kq = (idx>>6)*4;
          float4 v = *(const float4*)(g_G + ((size_t)(rt4*64+row)*T_ + t4)*256 + kq);
          sA4[(kq+0)*68 + row] = v.x;
          sA4[(kq+1)*68 + row] = v.y;
          sA4[(kq+2)*68 + row] = v.z;
          sA4[(kq+3)*68 + row] = v.w;
        }
        __syncthreads();
        const int r0 = (w5>>1)*8 + lh*4;
        const int cp = (w5&1)*16 + lx;
        ull acc4[4] = {0,0,0,0};
        #pragma unroll 1
        for (int kc=0;kc<8;kc++){
          #pragma unroll
          for (int kk=0;kk<32;kk++){
            int k = kc*32+kk;
            float4 av = *(const float4*)&sA4[k*68 + r0];
            ull b = *(const ull*)&wsm4[k*64 + cp*2];
            FMA2(acc4[0], pack2(av.x), b);
            FMA2(acc4[1], pack2(av.y), b);
            FMA2(acc4[2], pack2(av.z), b);
            FMA2(acc4[3], pack2(av.w), b);
          }
        }
        __syncthreads();
        const int gcol = ct4*64 + cp*2;
        #pragma unroll
        for (int j=0;j<4;j++){
          int b = rt4*64 + r0 + j;
          F2 u; u.u = acc4[j];
          *(float2*)(H + R_OFF + ((size_t)b*T_ + t4)*256 + gcol) = u.f;
        }
      }
    }

    // ---- sliced epoch arrive (grp4 signals nothing) ----
    __syncthreads();
    if (tid==0 && grp<4){
      __threadfence();
      int sl = (grp<3) ? grp*4+rt : 12+rt3;
      unsigned n = (grp<3) ? 8u : 4u;
      unsigned old = atomicAdd(&g_acnt[sl],1u);
      if (old % n == n-1u){
        g_eps[sl] = (int)(old/n) + 1;
      }
    }
  }
}

// ---------------- small heads ----------------
__global__ void concat_w(const float* __restrict__ W, const float* __restrict__ Wr1){
  int i = blockIdx.x*256 + threadIdx.x;
  g_Wcat[i] = (i < 65536) ? W[i] : Wr1[i-65536];
}

// fused y = gelu(H[:,127,:] @ Wp1^T) @ Wp2^T  (one block per batch row)
__global__ void y_fused(const float* __restrict__ H, const float* __restrict__ Wp1,
                        const float* __restrict__ Wp2, float* __restrict__ y){
  __shared__ float sh[256];
  __shared__ float sg[256];
  int b = blockIdx.x, tid = threadIdx.x;
  sh[tid] = H[((size_t)b*T_ + 127)*HID + tid];
  __syncthreads();
  const float* w = Wp1 + (size_t)tid*256;
  float s = 0.f;
  #pragma unroll 4
  for (int h=0; h<256; h+=4){
    float4 wv = *(const float4*)(w+h);
    s += sh[h]*wv.x + sh[h+1]*wv.y + sh[h+2]*wv.z + sh[h+3]*wv.w;
  }
  sg[tid] = gelu_f(s) * Wp2[tid];
  __syncthreads();
  for (int o=128;o;o>>=1){ if(tid<o) sg[tid]+=sg[tid+o]; __syncthreads(); }
  if(!tid) y[b]=sg[0];
}

__global__ void alpha_kernel(const float* __restrict__ P, float* __restrict__ alpha){
  __shared__ float s[256];
  int b=blockIdx.x, tid=threadIdx.x;
  s[tid] = g_WC[((size_t)b*T_+126)*256+tid] * P[((size_t)b*T_+127)*256+tid];
  __syncthreads();
  for (int o=128;o;o>>=1){ if(tid<o) s[tid]+=s[tid+o]; __syncthreads(); }
  if(!tid) alpha[b]=s[0]*(1.f/256.f);
}

__global__ void ce_kernel(const float* __restrict__ P, const int* __restrict__ neg){
  __shared__ float swc[256];
  __shared__ float red[16];
  int b=blockIdx.x, t=blockIdx.y, tid=threadIdx.x;
  int wid=tid>>5, lane=tid&31;
  const float* wc = g_WC + ((size_t)b*T_+t)*HID;
  for (int i=tid;i<256;i+=128) swc[i]=wc[i];
  __syncthreads();
  for (int j=wid;j<16;j+=4){
    int src = (j==0) ? b : neg[((size_t)t*15+(j-1))*BS + b];
    const float* p = P + ((size_t)src*T_ + t + 1)*256;
    float s=0.f;
    for (int d=lane; d<256; d+=32) s += swc[d]*p[d];
    #pragma unroll
    for (int o=16;o;o>>=1) s += __shfl_xor_sync(0xffffffffu, s, o);
    if (!lane) red[j] = s*(1.f/256.f);
  }
  __syncthreads();
  if (!tid){
    float m=red[0];
    #pragma unroll
    for (int j=1;j<16;j++) m=fmaxf(m,red[j]);
    float sum=0.f;
    #pragma unroll
    for (int j=0;j<16;j++) sum+=expf(red[j]-m);
    g_part[(size_t)t*BS+b] = m + logf(sum) - red[0];
  }
}

__global__ void loss_kernel(float* __restrict__ out){
  __shared__ float s[256];
  int tid=threadIdx.x;
  float a=0.f;
  for (int i=tid;i<(T_-1)*BS;i+=256) a+=g_part[i];
  s[tid]=a; __syncthreads();
  for (int o=128;o;o>>=1){ if(tid<o) s[tid]+=s[tid+o]; __syncthreads(); }
  if(!tid) out[0]=s[0]*(1.f/(float)BS);
}

extern "C" void kernel_launch(void* const* d_in, const int* in_sizes, int n_in,
                              void* d_out, int out_size){
  const float *P=(const float*)d_in[0], *Wih0=(const float*)d_in[1], *Whh0=(const float*)d_in[2],
              *bih0=(const float*)d_in[3], *bhh0=(const float*)d_in[4], *Wih1=(const float*)d_in[5],
              *Whh1=(const float*)d_in[6], *bih1=(const float*)d_in[7], *bhh1=(const float*)d_in[8],
              *W=(const float*)d_in[9],  *Wp1=(const float*)d_in[10], *Wp2=(const float*)d_in[11],
              *Wr1=(const float*)d_in[12], *Wr2=(const float*)d_in[13];
  const int* neg=(const int*)d_in[14];
  float* out=(float*)d_out;

  float *pGI0;
  cudaGetSymbolAddress((void**)&pGI0, g_GI0);

  cudaFuncSetAttribute(gru_kernel, cudaFuncAttributeMaxDynamicSharedMemorySize, SMEM_GRU);
  cudaFuncSetAttribute(gemm_tc, cudaFuncAttributeMaxDynamicSharedMemorySize, SMEM_GEMM);

  concat_w<<<512,256>>>(W, Wr1);                                                  // 1
  gemm_tc<<<dim3(6,256), 512, SMEM_GEMM>>>(P, 256, Wih0, bih0, pGI0, G3, 0, nullptr, 1); // 2
  pad_k<<<1,32>>>();                                                              // 3
  pad_k<<<1,32>>>();                                                              // 4
  pad_k<<<1,32>>>();                                                              // 5
  gru_kernel<<<NBG, 512, SMEM_GRU>>>(Whh0,bhh0,Wih1,bih1,Whh1,bhh1,Wr2,out);      // 6
  y_fused<<<BS,256>>>(out, Wp1, Wp2, out+Y_OFF);
  alpha_kernel<<<BS,256>>>(P, out+A_OFF);
  ce_kernel<<<dim3(BS, T_-1), 128>>>(P, neg);
  loss_kernel<<<1,256>>>(out+L_OFF);
}

// round 15
// speedup vs baseline: 1.5738x; 1.5738x over previous
#include <cuda_runtime.h>
#include <math.h>

#define BS 256
#define T_ 128
#define HID 256
#define G3 768
#define NBG 144
#define Y_OFF 8388608
#define R_OFF 8388864
#define A_OFF 16777472
#define L_OFF 16777728

#define SMEM_GRU ((96*260 + 64*260)*4)
#define SMEM_GEMM (2*2*32*130*4)

typedef unsigned long long ull;
typedef unsigned int u32;
union F2 { ull u; float2 f; };
#define FMA2(a,x,y) asm("fma.rn.f32x2 %0,%1,%2,%0;" : "+l"(a) : "l"(x), "l"(y))
__device__ __forceinline__ ull pack2(float v){ ull r; asm("mov.b64 %0,{%1,%1};" : "=l"(r) : "f"(v)); return r; }
__device__ __forceinline__ u32 tf32c(float x){ u32 u; asm("cvt.rna.tf32.f32 %0, %1;" : "=r"(u) : "f"(x)); return u; }
__device__ __forceinline__ void mma_tf32(float c[4], u32 a0,u32 a1,u32 a2,u32 a3, u32 b0,u32 b1){
  asm volatile("mma.sync.aligned.m16n8k8.row.col.f32.tf32.tf32.f32 "
    "{%0,%1,%2,%3}, {%4,%5,%6,%7}, {%8,%9}, {%0,%1,%2,%3};"
    : "+f"(c[0]), "+f"(c[1]), "+f"(c[2]), "+f"(c[3])
    : "r"(a0), "r"(a1), "r"(a2), "r"(a3), "r"(b0), "r"(b1));
}

__device__ float g_GI0[BS*T_*G3];     // [t][b][768]
__device__ float g_gi1[2][BS*G3];
__device__ float g_h1[2][BS*HID];
__device__ float g_h2[2][BS*HID];
__device__ float g_WC[BS*T_*HID];
__device__ float g_G[BS*T_*HID];
__device__ float g_Wcat[512*HID];
__device__ float g_part[(T_-1)*BS];
__device__ unsigned g_cnt;
__device__ unsigned g_gen;
__device__ volatile int g_ep[5];
__device__ unsigned g_gcnt[5];

__device__ __forceinline__ float sigm(float x){ return 1.f/(1.f+expf(-x)); }
__device__ __forceinline__ float gelu_f(float x){ return 0.5f*x*(1.f+erff(x*0.70710678118654752f)); }

__device__ __forceinline__ void gbar(unsigned nb){
  __syncthreads();
  if (threadIdx.x==0){
    __threadfence();
    unsigned g = *(volatile unsigned*)&g_gen;
    if (atomicAdd(&g_cnt,1u)==nb-1u){
      g_cnt = 0u;
      __threadfence();
      atomicAdd(&g_gen,1u);
    } else {
      while (*(volatile unsigned*)&g_gen == g) __nanosleep(32);
      __threadfence();
    }
  }
  __syncthreads();
}

__device__ __forceinline__ void wait_ep(int g, int need){
  while (g_ep[g] < need) __nanosleep(32);
}

// ======== gemm_tc (fp32, for GI0): C = A[Mx256] @ B[Nx256]^T + bias, row-permuted ========
__global__ void __launch_bounds__(512) gemm_tc(
    const float* __restrict__ A, int lda,
    const float* __restrict__ B,
    const float* __restrict__ bias,
    float* __restrict__ C, int ldc)
{
  extern __shared__ float gsm[];
  float* SA = gsm;
  float* SB = gsm + 2*32*130;
  const int bm = blockIdx.y*128, bn = blockIdx.x*128;
  const int tid = threadIdx.x;
  const int wg = tid>>5, tx = tid&31;
  const int lrow = tid>>3, lkq = tid&7;

  ull acc[4][4];
  #pragma unroll
  for (int c=0;c<4;c++){ acc[c][0]=0; acc[c][1]=0; acc[c][2]=0; acc[c][3]=0; }

  float4 pa0 = *(const float4*)(A + (size_t)(bm+lrow)*lda + lkq*4);
  float4 pa1 = *(const float4*)(A + (size_t)(bm+lrow+64)*lda + lkq*4);
  float4 pb0 = *(const float4*)(B + (size_t)(bn+lrow)*256 + lkq*4);
  float4 pb1 = *(const float4*)(B + (size_t)(bn+lrow+64)*256 + lkq*4);
  {
    float* dA = SA; float* dB = SB;
    dA[(lkq*4+0)*130+lrow]=pa0.x; dA[(lkq*4+1)*130+lrow]=pa0.y; dA[(lkq*4+2)*130+lrow]=pa0.z; dA[(lkq*4+3)*130+lrow]=pa0.w;
    dA[(lkq*4+0)*130+lrow+64]=pa1.x; dA[(lkq*4+1)*130+lrow+64]=pa1.y; dA[(lkq*4+2)*130+lrow+64]=pa1.z; dA[(lkq*4+3)*130+lrow+64]=pa1.w;
    dB[(lkq*4+0)*130+lrow]=pb0.x; dB[(lkq*4+1)*130+lrow]=pb0.y; dB[(lkq*4+2)*130+lrow]=pb0.z; dB[(lkq*4+3)*130+lrow]=pb0.w;
    dB[(lkq*4+0)*130+lrow+64]=pb1.x; dB[(lkq*4+1)*130+lrow+64]=pb1.y; dB[(lkq*4+2)*130+lrow+64]=pb1.z; dB[(lkq*4+3)*130+lrow+64]=pb1.w;
  }
  __syncthreads();

  #pragma unroll 1
  for (int kc=0; kc<8; kc++){
    const float* cA = SA + (kc&1)*4160;
    const float* cB = SB + (kc&1)*4160;
    if (kc<7){
      pa0 = *(const float4*)(A + (size_t)(bm+lrow)*lda + (kc+1)*32 + lkq*4);
      pa1 = *(const float4*)(A + (size_t)(bm+lrow+64)*lda + (kc+1)*32 + lkq*4);
      pb0 = *(const float4*)(B + (size_t)(bn+lrow)*256 + (kc+1)*32 + lkq*4);
      pb1 = *(const float4*)(B + (size_t)(bn+lrow+64)*256 + (kc+1)*32 + lkq*4);
    }
    #pragma unroll
    for (int k=0;k<32;k++){
      ull a0=*(const ull*)&cA[k*130 + wg*8];
      ull a1=*(const ull*)&cA[k*130 + wg*8+2];
      ull a2=*(const ull*)&cA[k*130 + wg*8+4];
      ull a3=*(const ull*)&cA[k*130 + wg*8+6];
      #pragma unroll
      for (int c=0;c<4;c++){
        ull bb = pack2(cB[k*130 + tx+32*c]);
        FMA2(acc[c][0],a0,bb); FMA2(acc[c][1],a1,bb);
        FMA2(acc[c][2],a2,bb); FMA2(acc[c][3],a3,bb);
      }
    }
    if (kc<7){
      float* dA = SA + ((kc+1)&1)*4160;
      float* dB = SB + ((kc+1)&1)*4160;
      dA[(lkq*4+0)*130+lrow]=pa0.x; dA[(lkq*4+1)*130+lrow]=pa0.y; dA[(lkq*4+2)*130+lrow]=pa0.z; dA[(lkq*4+3)*130+lrow]=pa0.w;
      dA[(lkq*4+0)*130+lrow+64]=pa1.x; dA[(lkq*4+1)*130+lrow+64]=pa1.y; dA[(lkq*4+2)*130+lrow+64]=pa1.z; dA[(lkq*4+3)*130+lrow+64]=pa1.w;
      dB[(lkq*4+0)*130+lrow]=pb0.x; dB[(lkq*4+1)*130+lrow]=pb0.y; dB[(lkq*4+2)*130+lrow]=pb0.z; dB[(lkq*4+3)*130+lrow]=pb0.w;
      dB[(lkq*4+0)*130+lrow+64]=pb1.x; dB[(lkq*4+1)*130+lrow+64]=pb1.y; dB[(lkq*4+2)*130+lrow+64]=pb1.z; dB[(lkq*4+3)*130+lrow+64]=pb1.w;
    }
    __syncthreads();
  }

  #pragma unroll
  for (int c=0;c<4;c++){
    int col = bn + tx + 32*c;
    float bv = bias ? bias[col] : 0.f;
    #pragma unroll
    for (int p=0;p<4;p++){
      F2 u; u.u = acc[c][p];
      float v[2] = {u.f.x, u.f.y};
      #pragma unroll
      for (int h=0;h<2;h++){
        float o = v[h] + bv;
        size_t r = (size_t)(bm + wg*8 + 2*p + h);
        r = (size_t)(r & 127)*256 + (r >> 7);   // [b][t] -> [t][b]
        C[r*ldc + col] = o;
      }
    }
  }
}

// ======== persistent fused GRU + heads: 144 CTAs x 512 threads, tf32 mma.sync ========
// grp0/1/2: GRU matmuls; grp3: WC/G; grp4: R
__global__ void __launch_bounds__(512,1) gru_kernel(
    const float* __restrict__ Whh0, const float* __restrict__ bhh0,
    const float* __restrict__ Wih1, const float* __restrict__ bih1,
    const float* __restrict__ Whh1, const float* __restrict__ bhh1,
    const float* __restrict__ Wr2,
    float* __restrict__ H)
{
  extern __shared__ float sm[];
  u32* smU = (u32*)sm;
  const int cta = blockIdx.x, tid = threadIdx.x;
  const int grp = cta>>5;
  const int warp = tid>>5, lane = tid&31;
  const int g = lane>>2, t = lane&3;

  // grp<3
  u32* wsmU = smU;               // [96][260]
  u32* sAU  = smU + 96*260;      // [64][260]
  float* sC = (float*)sAU;       // [64][100] reuse after crunch
  const int loc = cta&31;
  const int rt = loc>>3, ct = loc&7;
  const int wr = warp>>2, wc = warp&3;
  const bool is0 = (grp==0), is1 = (grp==1), is2 = (grp==2);
  const float* WB = is0 ? Whh0 : (is1 ? Wih1 : Whh1);
  const float* bvp = is0 ? bhh0 : (is1 ? bih1 : bhh1);
  const int erow = tid>>3, ehid = (tid&7)*4;   // epilogue assignment
  float4 bRv, bZv, bNv;

  // grp3
  u32* wsm3U = smU;              // [128][260]
  u32* sA3U  = smU + 128*260;    // [32][260]
  const int loc3 = cta - 96;
  const int rt3 = loc3>>2, ct3 = loc3&3;
  const int wr3 = warp>>3, wc3 = warp&7;
  // grp4
  u32* wsm4U = smU;              // [64][260]
  u32* sA4U  = smU + 64*260;     // [64][260]
  const int loc4 = cta - 128;
  const int rt4 = loc4>>2, ct4 = loc4&3;
  const int wr4 = warp>>2, wc4 = warp&3;

  if (grp < 3){
    bRv = *(const float4*)(bvp + ct*32 + ehid);
    bZv = *(const float4*)(bvp + 256 + ct*32 + ehid);
    bNv = *(const float4*)(bvp + 512 + ct*32 + ehid);
    for (int i = tid; i < 96*64; i += 512){
      int c = i>>6, kq = (i&63)*4;
      int gg = c>>5, cc = c&31;
      float4 w = *(const float4*)(WB + (size_t)(gg*256 + ct*32 + cc)*256 + kq);
      u32* d = wsmU + c*260 + kq;
      d[0]=tf32c(w.x); d[1]=tf32c(w.y); d[2]=tf32c(w.z); d[3]=tf32c(w.w);
    }
  } else if (grp == 3){
    for (int i = tid; i < 128*64; i += 512){
      int c = i>>6, kq = (i&63)*4;
      float4 w = *(const float4*)(g_Wcat + (size_t)(ct3*128 + c)*256 + kq);
      u32* d = wsm3U + c*260 + kq;
      d[0]=tf32c(w.x); d[1]=tf32c(w.y); d[2]=tf32c(w.z); d[3]=tf32c(w.w);
    }
  } else {
    for (int i = tid; i < 64*64; i += 512){
      int c = i>>6, kq = (i&63)*4;
      float4 w = *(const float4*)(Wr2 + (size_t)(ct4*64 + c)*256 + kq);
      u32* d = wsm4U + c*260 + kq;
      d[0]=tf32c(w.x); d[1]=tf32c(w.y); d[2]=tf32c(w.z); d[3]=tf32c(w.w);
    }
  }
  for (int i = cta*512 + tid; i < BS*HID; i += NBG*512){
    g_h1[0][i] = 0.f; g_h2[1][i] = 0.f;
  }
  if (cta==0 && tid==0){
    #pragma unroll
    for (int s=0;s<5;s++){ g_gcnt[s]=0u; g_ep[s]=0; }
  }
  gbar(NBG);

  #pragma unroll 1
  for (int p=0; p<T_+5; ++p){
    if (tid==0){
      if (grp==0){ wait_ep(0,p); wait_ep(1,p); }
      else if (grp==1){ wait_ep(0,p); wait_ep(2,p); }
      else if (grp==2){ wait_ep(1,p); wait_ep(2,p); }
      else if (grp==3){ wait_ep(2,p); }
      else { wait_ep(3,p-1); }
      __threadfence();
    }
    __syncthreads();

    if (grp < 3){
      bool active = (is0 && p<T_) || (is1 && p>=1 && p<=T_) || (is2 && p>=2 && p<=T_+1);
      if (active){
        const float* Ain = is2 ? g_h2[(p-1)&1] : g_h1[p&1];
        // A load + tf32 convert, row-major [64][260]
        {
          const int arow = tid>>3, akq = (tid&7)*4;
          const float* arp = Ain + (size_t)(rt*64+arow)*256 + akq;
          u32* dst = sAU + arow*260 + akq;
          #pragma unroll
          for (int c=0;c<8;c++){
            float4 v = *(const float4*)(arp + c*32);
            uint4 u; u.x=tf32c(v.x); u.y=tf32c(v.y); u.z=tf32c(v.z); u.w=tf32c(v.w);
            *(uint4*)(dst + c*32) = u;
          }
        }
        __syncthreads();

        float c[3][4] = {};
        const u32* aR0 = sAU + (wr*16+g)*260 + t;
        const u32* aR1 = aR0 + 8*260;
        const u32* b0p = wsmU + (wc*24+g)*260 + t;
        const u32* b1p = b0p + 8*260;
        const u32* b2p = b0p + 16*260;
        #pragma unroll 8
        for (int ks=0; ks<32; ks++){
          int off = ks*8;
          u32 a0=aR0[off], a2=aR0[off+4], a1=aR1[off], a3=aR1[off+4];
          mma_tf32(c[0], a0,a1,a2,a3, b0p[off], b0p[off+4]);
          mma_tf32(c[1], a0,a1,a2,a3, b1p[off], b1p[off+4]);
          mma_tf32(c[2], a0,a1,a2,a3, b2p[off], b2p[off+4]);
        }
        __syncthreads();   // done reading sA; reuse as C

        // store C gate-interleaved: sC[row][hid*3+gate]
        {
          int r0 = wr*16 + g;
          #pragma unroll
          for (int nt=0;nt<3;nt++){
            int c0 = wc*24 + nt*8 + 2*t, c1 = c0+1;
            sC[r0*100 + (c0&31)*3 + (c0>>5)] = c[nt][0];
            sC[r0*100 + (c1&31)*3 + (c1>>5)] = c[nt][1];
            sC[(r0+8)*100 + (c0&31)*3 + (c0>>5)] = c[nt][2];
            sC[(r0+8)*100 + (c1&31)*3 + (c1>>5)] = c[nt][3];
          }
        }
        __syncthreads();

        // epilogue: thread owns (row=erow, hids ehid..ehid+3)
        {
          float4 f0 = *(float4*)&sC[erow*100 + ehid*3];
          float4 f1 = *(float4*)&sC[erow*100 + ehid*3 + 4];
          float4 f2 = *(float4*)&sC[erow*100 + ehid*3 + 8];
          float cr[4]={f0.x,f0.w,f1.z,f2.y};
          float cz[4]={f0.y,f1.x,f1.w,f2.z};
          float cn[4]={f0.z,f1.y,f2.x,f2.w};
          float br[4]={bRv.x,bRv.y,bRv.z,bRv.w};
          float bz[4]={bZv.x,bZv.y,bZv.z,bZv.w};
          float bn[4]={bNv.x,bNv.y,bNv.z,bNv.w};
          int b = rt*64 + erow;
          int colg = ct*32 + ehid;
          if (is1){
            float* og = g_gi1[p&1] + (size_t)b*G3;
            float4 o;
            o.x=cr[0]+br[0]; o.y=cr[1]+br[1]; o.z=cr[2]+br[2]; o.w=cr[3]+br[3];
            *(float4*)(og + colg) = o;
            o.x=cz[0]+bz[0]; o.y=cz[1]+bz[1]; o.z=cz[2]+bz[2]; o.w=cz[3]+bz[3];
            *(float4*)(og + 256 + colg) = o;
            o.x=cn[0]+bn[0]; o.y=cn[1]+bn[1]; o.z=cn[2]+bn[2]; o.w=cn[3]+bn[3];
            *(float4*)(og + 512 + colg) = o;
          } else {
            const float* gi = is0 ? (g_GI0 + ((size_t)p*256 + b)*G3)
                                  : (g_gi1[(p-1)&1] + (size_t)b*G3);
            float4 gR4 = *(const float4*)(gi + colg);
            float4 gZ4 = *(const float4*)(gi + 256 + colg);
            float4 gN4 = *(const float4*)(gi + 512 + colg);
            const float* hs = is0 ? g_h1[p&1] : g_h2[(p-1)&1];
            float4 h4 = *(const float4*)(hs + b*HID + colg);
            float gr[4]={gR4.x,gR4.y,gR4.z,gR4.w};
            float gz[4]={gZ4.x,gZ4.y,gZ4.z,gZ4.w};
            float gn[4]={gN4.x,gN4.y,gN4.z,gN4.w};
            float ho[4]={h4.x,h4.y,h4.z,h4.w};
            float hn[4];
            #pragma unroll
            for (int i=0;i<4;i++){
              float r = sigm(gr[i] + cr[i] + br[i]);
              float z = sigm(gz[i] + cz[i] + bz[i]);
              float n = tanhf(gn[i] + r*(cn[i] + bn[i]));
              hn[i] = (1.f-z)*n + z*ho[i];
            }
            float4 o; o.x=hn[0]; o.y=hn[1]; o.z=hn[2]; o.w=hn[3];
            if (is0){
              *(float4*)(g_h1[(p+1)&1] + b*HID + colg) = o;
            } else {
              *(float4*)(g_h2[p&1] + b*HID + colg) = o;
              *(float4*)(H + ((size_t)b*T_ + (p-2))*HID + colg) = o;
            }
          }
        }
      }
    } else if (grp == 3){
      if (p>=3 && p<=T_+2){
        const int t3 = p-3;
        #pragma unroll
        for (int q=0;q<4;q++){
          int idx = tid + 512*q;
          int row = idx & 31, kq = (idx>>5)*4;
          float4 v = *(const float4*)(H + ((size_t)(rt3*32+row)*T_ + t3)*256 + kq);
          uint4 u; u.x=tf32c(v.x); u.y=tf32c(v.y); u.z=tf32c(v.z); u.w=tf32c(v.w);
          *(uint4*)(sA3U + row*260 + kq) = u;
        }
        __syncthreads();
        float c[2][4] = {};
        const u32* aR0 = sA3U + (wr3*16+g)*260 + t;
        const u32* aR1 = aR0 + 8*260;
        const u32* b0p = wsm3U + (wc3*16+g)*260 + t;
        const u32* b1p = b0p + 8*260;
        #pragma unroll 8
        for (int ks=0; ks<32; ks++){
          int off = ks*8;
          u32 a0=aR0[off], a2=aR0[off+4], a1=aR1[off], a3=aR1[off+4];
          mma_tf32(c[0], a0,a1,a2,a3, b0p[off], b0p[off+4]);
          mma_tf32(c[1], a0,a1,a2,a3, b1p[off], b1p[off+4]);
        }
        int r0 = rt3*32 + wr3*16 + g;
        #pragma unroll
        for (int nt=0;nt<2;nt++){
          int colc = ct3*128 + wc3*16 + nt*8 + 2*t;
          float2 v0, v1;
          v0.x=c[nt][0]; v0.y=c[nt][1]; v1.x=c[nt][2]; v1.y=c[nt][3];
          if (colc < 256){
            *(float2*)(g_WC + ((size_t)r0*T_ + t3)*256 + colc) = v0;
            *(float2*)(g_WC + ((size_t)(r0+8)*T_ + t3)*256 + colc) = v1;
          } else {
            v0.x=gelu_f(v0.x); v0.y=gelu_f(v0.y); v1.x=gelu_f(v1.x); v1.y=gelu_f(v1.y);
            *(float2*)(g_G + ((size_t)r0*T_ + t3)*256 + (colc-256)) = v0;
            *(float2*)(g_G + ((size_t)(r0+8)*T_ + t3)*256 + (colc-256)) = v1;
          }
        }
        __syncthreads();
      }
    } else {
      if (p>=5 && p<=T_+4){
        const int t4 = p-5;
        #pragma unroll
        for (int q=0;q<8;q++){
          int idx = tid + 512*q;
          int row = idx & 63, kq = (idx>>6)*4;
          float4 v = *(const float4*)(g_G + ((size_t)(rt4*64+row)*T_ + t4)*256 + kq);
          uint4 u; u.x=tf32c(v.x); u.y=tf32c(v.y); u.z=tf32c(v.z); u.w=tf32c(v.w);
          *(uint4*)(sA4U + row*260 + kq) = u;
        }
        __syncthreads();
        float c[2][4] = {};
        const u32* aR0 = sA4U + (wr4*16+g)*260 + t;
        const u32* aR1 = aR0 + 8*260;
        const u32* b0p = wsm4U + (wc4*16+g)*260 + t;
        const u32* b1p = b0p + 8*260;
        #pragma unroll 8
        for (int ks=0; ks<32; ks++){
          int off = ks*8;
          u32 a0=aR0[off], a2=aR0[off+4], a1=aR1[off], a3=aR1[off+4];
          mma_tf32(c[0], a0,a1,a2,a3, b0p[off], b0p[off+4]);
          mma_tf32(c[1], a0,a1,a2,a3, b1p[off], b1p[off+4]);
        }
        int r0 = rt4*64 + wr4*16 + g;
        #pragma unroll
        for (int nt=0;nt<2;nt++){
          int colc = ct4*64 + wc4*16 + nt*8 + 2*t;
          float2 v0, v1;
          v0.x=c[nt][0]; v0.y=c[nt][1]; v1.x=c[nt][2]; v1.y=c[nt][3];
          *(float2*)(H + R_OFF + ((size_t)r0*T_ + t4)*256 + colc) = v0;
          *(float2*)(H + R_OFF + ((size_t)(r0+8)*T_ + t4)*256 + colc) = v1;
        }
        __syncthreads();
      }
    }

    __syncthreads();
    if (tid==0){
      __threadfence();
      unsigned n = (grp==4) ? 16u : 32u;
      unsigned old = atomicAdd(&g_gcnt[grp],1u);
      if (old % n == n-1u){
        g_ep[grp] = (int)(old/n) + 1;
      }
    }
  }
}

// ---------------- small heads ----------------
__global__ void concat_w(const float* __restrict__ W, const float* __restrict__ Wr1){
  int i = blockIdx.x*256 + threadIdx.x;
  g_Wcat[i] = (i < 65536) ? W[i] : Wr1[i-65536];
}

__global__ void y_fused(const float* __restrict__ H, const float* __restrict__ Wp1,
                        const float* __restrict__ Wp2, float* __restrict__ y){
  __shared__ float sh[256];
  __shared__ float sg[256];
  int b = blockIdx.x, tid = threadIdx.x;
  sh[tid] = H[((size_t)b*T_ + 127)*HID + tid];
  __syncthreads();
  const float* w = Wp1 + (size_t)tid*256;
  float s = 0.f;
  #pragma unroll 4
  for (int h=0; h<256; h+=4){
    float4 wv = *(const float4*)(w+h);
    s += sh[h]*wv.x + sh[h+1]*wv.y + sh[h+2]*wv.z + sh[h+3]*wv.w;
  }
  sg[tid] = gelu_f(s) * Wp2[tid];
  __syncthreads();
  for (int o=128;o;o>>=1){ if(tid<o) sg[tid]+=sg[tid+o]; __syncthreads(); }
  if(!tid) y[b]=sg[0];
}

__global__ void alpha_kernel(const float* __restrict__ P, float* __restrict__ alpha){
  __shared__ float s[256];
  int b=blockIdx.x, tid=threadIdx.x;
  s[tid] = g_WC[((size_t)b*T_+126)*256+tid] * P[((size_t)b*T_+127)*256+tid];
  __syncthreads();
  for (int o=128;o;o>>=1){ if(tid<o) s[tid]+=s[tid+o]; __syncthreads(); }
  if(!tid) alpha[b]=s[0]*(1.f/256.f);
}

__global__ void ce_kernel(const float* __restrict__ P, const int* __restrict__ neg){
  __shared__ float swc[256];
  __shared__ float red[16];
  int b=blockIdx.x, t=blockIdx.y, tid=threadIdx.x;
  int wid=tid>>5, lane=tid&31;
  const float* wc = g_WC + ((size_t)b*T_+t)*HID;
  for (int i=tid;i<256;i+=128) swc[i]=wc[i];
  __syncthreads();
  for (int j=wid;j<16;j+=4){
    int src = (j==0) ? b : neg[((size_t)t*15+(j-1))*BS + b];
    const float* p = P + ((size_t)src*T_ + t + 1)*256;
    float s=0.f;
    for (int d=lane; d<256; d+=32) s += swc[d]*p[d];
    #pragma unroll
    for (int o=16;o;o>>=1) s += __shfl_xor_sync(0xffffffffu, s, o);
    if (!lane) red[j] = s*(1.f/256.f);
  }
  __syncthreads();
  if (!tid){
    float m=red[0];
    #pragma unroll
    for (int j=1;j<16;j++) m=fmaxf(m,red[j]);
    float sum=0.f;
    #pragma unroll
    for (int j=0;j<16;j++) sum+=expf(red[j]-m);
    g_part[(size_t)t*BS+b] = m + logf(sum) - red[0];
  }
}

__global__ void loss_kernel(float* __restrict__ out){
  __shared__ float s[256];
  int tid=threadIdx.x;
  float a=0.f;
  for (int i=tid;i<(T_-1)*BS;i+=256) a+=g_part[i];
  s[tid]=a; __syncthreads();
  for (int o=128;o;o>>=1){ if(tid<o) s[tid]+=s[tid+o]; __syncthreads(); }
  if(!tid) out[0]=s[0]*(1.f/(float)BS);
}

extern "C" void kernel_launch(void* const* d_in, const int* in_sizes, int n_in,
                              void* d_out, int out_size){
  const float *P=(const float*)d_in[0], *Wih0=(const float*)d_in[1], *Whh0=(const float*)d_in[2],
              *bih0=(const float*)d_in[3], *bhh0=(const float*)d_in[4], *Wih1=(const float*)d_in[5],
              *Whh1=(const float*)d_in[6], *bih1=(const float*)d_in[7], *bhh1=(const float*)d_in[8],
              *W=(const float*)d_in[9],  *Wp1=(const float*)d_in[10], *Wp2=(const float*)d_in[11],
              *Wr1=(const float*)d_in[12], *Wr2=(const float*)d_in[13];
  const int* neg=(const int*)d_in[14];
  float* out=(float*)d_out;

  float *pGI0;
  cudaGetSymbolAddress((void**)&pGI0, g_GI0);

  cudaFuncSetAttribute(gru_kernel, cudaFuncAttributeMaxDynamicSharedMemorySize, SMEM_GRU);
  cudaFuncSetAttribute(gemm_tc, cudaFuncAttributeMaxDynamicSharedMemorySize, SMEM_GEMM);

  concat_w<<<512,256>>>(W, Wr1);
  gemm_tc<<<dim3(6,256), 512, SMEM_GEMM>>>(P, 256, Wih0, bih0, pGI0, G3);
  gru_kernel<<<NBG, 512, SMEM_GRU>>>(Whh0,bhh0,Wih1,bih1,Whh1,bhh1,Wr2,out);
  y_fused<<<BS,256>>>(out, Wp1, Wp2, out+Y_OFF);
  alpha_kernel<<<BS,256>>>(P, out+A_OFF);
  ce_kernel<<<dim3(BS, T_-1), 128>>>(P, neg);
  loss_kernel<<<1,256>>>(out+L_OFF);
}